// round 15
// baseline (speedup 1.0000x reference)
#include <cuda_runtime.h>
#include <cuda_fp16.h>
#include <cuda_bf16.h>
#include <math.h>
#include <stdint.h>

#define EPSF 1e-7f
#define MAX_TANHF (1.0f - 1e-6f)

constexpr int F = 128;
constexpr int NMAX = 8192;
constexpr int TM = 32;    // rows per GEMM block
constexpr int NTH = 128;  // 4 warps

__device__ __half g_Vh[NMAX * F];     // log0(h), fp16 (spmm gather payload)
__device__ float  g_C [NMAX * 2 * F]; // log0([x ; neigh]) fp32

// ---------------------------------------------------------------------------
__device__ __forceinline__ float warp_sum(float v) {
    v += __shfl_xor_sync(0xffffffffu, v, 16);
    v += __shfl_xor_sync(0xffffffffu, v, 8);
    v += __shfl_xor_sync(0xffffffffu, v, 4);
    v += __shfl_xor_sync(0xffffffffu, v, 2);
    v += __shfl_xor_sync(0xffffffffu, v, 1);
    return v;
}
__device__ __forceinline__ float quad_sum(float v) {
    v += __shfl_xor_sync(0xffffffffu, v, 1);
    v += __shfl_xor_sync(0xffffffffu, v, 2);
    return v;
}
__device__ __forceinline__ float dot4(float4 a, float4 b) {
    return a.x * b.x + a.y * b.y + a.z * b.z + a.w * b.w;
}
__device__ __forceinline__ uint32_t bfpk(float a, float b) {
    __nv_bfloat162 t = __floats2bfloat162_rn(a, b);
    return *reinterpret_cast<uint32_t*>(&t);
}
__device__ __forceinline__ void split4(float4 v, uint2& hi, uint2& lo) {
    float h0 = __bfloat162float(__float2bfloat16_rn(v.x));
    float h1 = __bfloat162float(__float2bfloat16_rn(v.y));
    float h2 = __bfloat162float(__float2bfloat16_rn(v.z));
    float h3 = __bfloat162float(__float2bfloat16_rn(v.w));
    hi.x = bfpk(h0, h1); hi.y = bfpk(h2, h3);
    lo.x = bfpk(v.x - h0, v.y - h1); lo.y = bfpk(v.z - h2, v.w - h3);
}
__device__ __forceinline__ void mma_bf(float* c, const uint32_t* a,
                                       uint32_t b0, uint32_t b1) {
    asm volatile("mma.sync.aligned.m16n8k16.row.col.f32.bf16.bf16.f32 "
        "{%0,%1,%2,%3}, {%4,%5,%6,%7}, {%8,%9}, {%0,%1,%2,%3};"
        : "+f"(c[0]), "+f"(c[1]), "+f"(c[2]), "+f"(c[3])
        : "r"(a[0]), "r"(a[1]), "r"(a[2]), "r"(a[3]), "r"(b0), "r"(b1));
}
__device__ __forceinline__ void hadd_coef(float ne2, float xs, float y2,
                                          float& sc, float& c1, float& c2, float& inv) {
    float ne = fmaxf(sqrtf(ne2), EPSF);
    sc = tanhf(ne) / ne;
    float xy = sc * xs;
    float x2 = sc * sc * ne2;
    c1 = 1.f + 2.f * xy + y2;
    c2 = 1.f - x2;
    inv = 1.f / fmaxf(1.f + 2.f * xy + x2 * y2, EPSF);
}

// smem layout
__host__ __device__ constexpr int rsK(int K) { return K * 2 + 16; }
constexpr int SM_BIAS = 0;      // 128 floats
constexpr int SM_SROW = 512;    // 32 floats
constexpr int SM_REDN = 640;    // 64 floats [row][ch]
constexpr int SM_REDX = 896;    // 64 floats
constexpr int SM_REDM = 1152;   // 64 floats
constexpr int SM_REDY = 1408;   // 2 floats
constexpr int SM_AHI  = 1536;
__host__ __device__ constexpr int smAlo(int KA) { return SM_AHI + TM * rsK(KA); }
__host__ __device__ constexpr int smBhi(int KA) { return smAlo(KA) + TM * rsK(KA); }
__host__ __device__ constexpr int smBlo(int KA, int KB) { return smBhi(KA) + 128 * rsK(KB); }
__host__ __device__ constexpr int smTot(int KA, int KB) { return smBlo(KA, KB) + 128 * rsK(KB); }

// fill a 128-k B chunk: Bg[K][128] fp32 -> smem [n][k] bf16 hi/lo (stride rsK(128))
template <int KA>
__device__ __forceinline__ void fill_B128(char* sm, const float* __restrict__ Bg,
                                          int kbase, int tid) {
    constexpr int RB = rsK(128);
    for (int i = tid; i < 128 * 32; i += NTH) {
        int n = i & 127, k0 = (i >> 7) * 4;
        float4 v = make_float4(Bg[(size_t)(kbase + k0 + 0) * 128 + n],
                               Bg[(size_t)(kbase + k0 + 1) * 128 + n],
                               Bg[(size_t)(kbase + k0 + 2) * 128 + n],
                               Bg[(size_t)(kbase + k0 + 3) * 128 + n]);
        uint2 hi, lo;
        split4(v, hi, lo);
        *(uint2*)(sm + smBhi(KA)      + n * RB + k0 * 2) = hi;
        *(uint2*)(sm + smBlo(KA, 128) + n * RB + k0 * 2) = lo;
    }
}

// 8 kt (=128 k) of bf16-split MMAs; warp patch m16 x n64 (8 nt groups)
template <int RA, int RB>
__device__ __forceinline__ void mma_loop8(const char* Ah, const char* Al,
                                          const char* Bh, const char* Bl,
                                          float acc[8][4], int tig) {
#pragma unroll
    for (int kt = 0; kt < 8; kt++) {
        int kb = kt * 32 + tig * 4;
        uint32_t ahi[4], alo[4];
        ahi[0] = *(const uint32_t*)(Ah + kb);
        ahi[1] = *(const uint32_t*)(Ah + 8 * RA + kb);
        ahi[2] = *(const uint32_t*)(Ah + kb + 16);
        ahi[3] = *(const uint32_t*)(Ah + 8 * RA + kb + 16);
        alo[0] = *(const uint32_t*)(Al + kb);
        alo[1] = *(const uint32_t*)(Al + 8 * RA + kb);
        alo[2] = *(const uint32_t*)(Al + kb + 16);
        alo[3] = *(const uint32_t*)(Al + 8 * RA + kb + 16);
#pragma unroll
        for (int nt = 0; nt < 8; nt++) {
            const char* bh = Bh + nt * 8 * RB + kb;
            const char* bl = Bl + nt * 8 * RB + kb;
            uint32_t b0 = *(const uint32_t*)(bh);
            uint32_t b1 = *(const uint32_t*)(bh + 16);
            uint32_t l0 = *(const uint32_t*)(bl);
            uint32_t l1 = *(const uint32_t*)(bl + 16);
            mma_bf(acc[nt], ahi, b0, b1);
            mma_bf(acc[nt], ahi, l0, l1);
            mma_bf(acc[nt], alo, b0, b1);
        }
    }
}

// ---------------------------------------------------------------------------
// Stage 1: Vh = fp16( log0( h_add( exp0( log0(x) @ embed ), ebias ) ) )
// ---------------------------------------------------------------------------
__global__ void __launch_bounds__(NTH)
k_mma1(const float* __restrict__ x, const float* __restrict__ Bg,
       const float* __restrict__ ebias, __half* __restrict__ Vh) {
    constexpr int RA = rsK(128), RB = rsK(128);
    extern __shared__ char sm[];
    int tid = threadIdx.x, lane = tid & 31, w = tid >> 5;
    int g = lane >> 2, tig = lane & 3;
    int rs = w >> 1, ch = w & 1;      // row slab / col half
    int row0 = blockIdx.x * TM;

    ((float*)(sm + SM_BIAS))[tid] = ebias[tid];

    const float4* X4 = (const float4*)x;
    float* srow = (float*)(sm + SM_SROW);
    for (int rr = 0; rr < 8; rr++) {
        int row = w * 8 + rr;
        float4 xv = X4[(size_t)(row0 + row) * 32 + lane];
        float n2 = warp_sum(dot4(xv, xv));
        float n = fmaxf(sqrtf(n2), EPSF);
        if (lane == 0) srow[row] = atanhf(fminf(n, MAX_TANHF)) / n;
    }
    fill_B128<128>(sm, Bg, 0, tid);
    __syncthreads();

    for (int i = tid; i < TM * 32; i += NTH) {
        int row = i >> 5, cg = i & 31;
        float s = srow[row];
        float4 v = X4[(size_t)(row0 + row) * 32 + cg];
        v.x *= s; v.y *= s; v.z *= s; v.w *= s;
        uint2 hi, lo;
        split4(v, hi, lo);
        *(uint2*)(sm + SM_AHI      + row * RA + cg * 8) = hi;
        *(uint2*)(sm + smAlo(128)  + row * RA + cg * 8) = lo;
    }
    __syncthreads();

    float acc[8][4] = {};
    mma_loop8<RA, RB>(sm + SM_AHI       + (rs * 16 + g) * RA,
                      sm + smAlo(128)   + (rs * 16 + g) * RA,
                      sm + smBhi(128)      + (ch * 64 + g) * RB,
                      sm + smBlo(128, 128) + (ch * 64 + g) * RB, acc, tig);

    // ---- epilogue (cross-warp reductions via smem) ----
    int r0l = rs * 16 + g, r1l = r0l + 8;
    const float* eb = (const float*)(sm + SM_BIAS) + ch * 64;
    float n0 = 0, n1 = 0, xs0 = 0, xs1 = 0, ysp = 0;
#pragma unroll
    for (int nt = 0; nt < 8; nt++) {
        float2 e = *(const float2*)(eb + nt * 8 + tig * 2);
        n0  += acc[nt][0] * acc[nt][0] + acc[nt][1] * acc[nt][1];
        n1  += acc[nt][2] * acc[nt][2] + acc[nt][3] * acc[nt][3];
        xs0 += acc[nt][0] * e.x + acc[nt][1] * e.y;
        xs1 += acc[nt][2] * e.x + acc[nt][3] * e.y;
        ysp += e.x * e.x + e.y * e.y;
    }
    float n0q = quad_sum(n0), n1q = quad_sum(n1);
    float x0q = quad_sum(xs0), x1q = quad_sum(xs1);
    float yq = quad_sum(ysp);
    float* redN = (float*)(sm + SM_REDN);
    float* redX = (float*)(sm + SM_REDX);
    float* redY = (float*)(sm + SM_REDY);
    if (tig == 0) {
        redN[r0l * 2 + ch] = n0q; redN[r1l * 2 + ch] = n1q;
        redX[r0l * 2 + ch] = x0q; redX[r1l * 2 + ch] = x1q;
        if (g == 0 && rs == 0) redY[ch] = yq;
    }
    __syncthreads();
    float ne20 = redN[r0l * 2] + redN[r0l * 2 + 1];
    float ne21 = redN[r1l * 2] + redN[r1l * 2 + 1];
    float xss0 = redX[r0l * 2] + redX[r0l * 2 + 1];
    float xss1 = redX[r1l * 2] + redX[r1l * 2 + 1];
    float y2 = redY[0] + redY[1];

    float sc0, c10, c20, iv0, sc1, c11, c21, iv1;
    hadd_coef(ne20, xss0, y2, sc0, c10, c20, iv0);
    hadd_coef(ne21, xss1, y2, sc1, c11, c21, iv1);

    float m0 = 0, m1 = 0;
#pragma unroll
    for (int nt = 0; nt < 8; nt++) {
        float2 e = *(const float2*)(eb + nt * 8 + tig * 2);
        float r00 = (c10 * sc0 * acc[nt][0] + c20 * e.x) * iv0;
        float r01 = (c10 * sc0 * acc[nt][1] + c20 * e.y) * iv0;
        float r10 = (c11 * sc1 * acc[nt][2] + c21 * e.x) * iv1;
        float r11 = (c11 * sc1 * acc[nt][3] + c21 * e.y) * iv1;
        m0 += r00 * r00 + r01 * r01;
        m1 += r10 * r10 + r11 * r11;
        acc[nt][0] = r00; acc[nt][1] = r01; acc[nt][2] = r10; acc[nt][3] = r11;
    }
    float m0q = quad_sum(m0), m1q = quad_sum(m1);
    float* redM = (float*)(sm + SM_REDM);
    if (tig == 0) { redM[r0l * 2 + ch] = m0q; redM[r1l * 2 + ch] = m1q; }
    __syncthreads();
    float nr0 = fmaxf(sqrtf(redM[r0l * 2] + redM[r0l * 2 + 1]), EPSF);
    float nr1 = fmaxf(sqrtf(redM[r1l * 2] + redM[r1l * 2 + 1]), EPSF);
    float s0 = atanhf(fminf(nr0, MAX_TANHF)) / nr0;
    float s1 = atanhf(fminf(nr1, MAX_TANHF)) / nr1;

    size_t r0g = (size_t)(row0 + r0l) * 128 + ch * 64;
    size_t r1g = (size_t)(row0 + r1l) * 128 + ch * 64;
#pragma unroll
    for (int nt = 0; nt < 8; nt++) {
        int col = nt * 8 + tig * 2;
        half2 h0 = __floats2half2_rn(acc[nt][0] * s0, acc[nt][1] * s0);
        half2 h1 = __floats2half2_rn(acc[nt][2] * s1, acc[nt][3] * s1);
        *(uint32_t*)(Vh + r0g + col) = *reinterpret_cast<uint32_t*>(&h0);
        *(uint32_t*)(Vh + r1g + col) = *reinterpret_cast<uint32_t*>(&h1);
    }
}

// ---------------------------------------------------------------------------
// Stage 2: C = log0([x ; exp0(adj @ Vh)]) — warp/row, fp16 gathers
// ---------------------------------------------------------------------------
__global__ void k_spmm_fused(const float* __restrict__ adj,
                             const float* __restrict__ x,
                             const __half* __restrict__ Vh, int N) {
    int warp = (blockIdx.x * blockDim.x + threadIdx.x) >> 5;
    int lane = threadIdx.x & 31;
    if (warp >= N) return;

    const uint2* V2 = (const uint2*)Vh;
    const float4* arow = (const float4*)(adj + (size_t)warp * N);
    float4 acc = make_float4(0.f, 0.f, 0.f, 0.f);

    int nq = N / 4;
    float4 a_cur = __ldcs(arow + lane);
    for (int jb = 0; jb < nq; jb += 32) {
        float4 a_nxt = make_float4(0.f, 0.f, 0.f, 0.f);
        if (jb + 32 < nq) a_nxt = __ldcs(arow + jb + 32 + lane);
#pragma unroll
        for (int c = 0; c < 4; c++) {
            float av = (c == 0) ? a_cur.x : (c == 1) ? a_cur.y
                                : (c == 2) ? a_cur.z : a_cur.w;
            unsigned m = __ballot_sync(0xffffffffu, av != 0.0f);
            while (m) {
                int b = __ffs(m) - 1;
                m &= m - 1;
                float aval = __shfl_sync(0xffffffffu, av, b);
                int j = (jb + b) * 4 + c;
                uint2 vr = V2[(size_t)j * 32 + lane];
                half2 h0 = *reinterpret_cast<half2*>(&vr.x);
                half2 h1 = *reinterpret_cast<half2*>(&vr.y);
                float2 f0 = __half22float2(h0);
                float2 f1 = __half22float2(h1);
                acc.x += aval * f0.x;
                acc.y += aval * f0.y;
                acc.z += aval * f1.x;
                acc.w += aval * f1.y;
            }
        }
        a_cur = a_nxt;
    }

    float nn2 = warp_sum(dot4(acc, acc));
    float nn = fmaxf(sqrtf(nn2), EPSF);
    float e = tanhf(nn) / nn;
    float4 ng = make_float4(acc.x * e, acc.y * e, acc.z * e, acc.w * e);

    float4 xv = ((const float4*)x)[(size_t)warp * 32 + lane];
    float nx2 = warp_sum(dot4(xv, xv));
    float ng2 = e * e * nn2;
    float nc = fmaxf(sqrtf(nx2 + ng2), EPSF);
    float s = atanhf(fminf(nc, MAX_TANHF)) / nc;

    float4* C4 = (float4*)g_C;
    C4[(size_t)warp * 64 + lane]      = make_float4(xv.x * s, xv.y * s, xv.z * s, xv.w * s);
    C4[(size_t)warp * 64 + 32 + lane] = make_float4(ng.x * s, ng.y * s, ng.z * s, ng.w * s);
}

// ---------------------------------------------------------------------------
// Stage 3: out = h_add( exp0( C @ layer ), lbias ), K=256, B chunked 2 x 128k
// ---------------------------------------------------------------------------
__global__ void __launch_bounds__(NTH)
k_mma3(const float* __restrict__ A, const float* __restrict__ Bg,
       const float* __restrict__ lbias, float* __restrict__ out) {
    constexpr int RA = rsK(256), RB = rsK(128);
    extern __shared__ char sm[];
    int tid = threadIdx.x, lane = tid & 31, w = tid >> 5;
    int g = lane >> 2, tig = lane & 3;
    int rs = w >> 1, ch = w & 1;
    int row0 = blockIdx.x * TM;

    ((float*)(sm + SM_BIAS))[tid] = lbias[tid];

    // A fill: rows of g_C, full K=256
    const float4* A4 = (const float4*)A;
    for (int i = tid; i < TM * 64; i += NTH) {
        int row = i >> 6, cg = i & 63;
        float4 v = A4[(size_t)(row0 + row) * 64 + cg];
        uint2 hi, lo;
        split4(v, hi, lo);
        *(uint2*)(sm + SM_AHI     + row * RA + cg * 8) = hi;
        *(uint2*)(sm + smAlo(256) + row * RA + cg * 8) = lo;
    }

    float acc[8][4] = {};
    const char* Ah = sm + SM_AHI     + (rs * 16 + g) * RA;
    const char* Al = sm + smAlo(256) + (rs * 16 + g) * RA;
    const char* Bh = sm + smBhi(256)      + (ch * 64 + g) * RB;
    const char* Bl = sm + smBlo(256, 128) + (ch * 64 + g) * RB;
#pragma unroll
    for (int kc = 0; kc < 2; kc++) {
        __syncthreads();
        fill_B128<256>(sm, Bg, kc * 128, tid);
        __syncthreads();
        mma_loop8<RA, RB>(Ah + kc * 256, Al + kc * 256, Bh, Bl, acc, tig);
    }

    int r0l = rs * 16 + g, r1l = r0l + 8;
    const float* eb = (const float*)(sm + SM_BIAS) + ch * 64;
    float n0 = 0, n1 = 0, xs0 = 0, xs1 = 0, ysp = 0;
#pragma unroll
    for (int nt = 0; nt < 8; nt++) {
        float2 e = *(const float2*)(eb + nt * 8 + tig * 2);
        n0  += acc[nt][0] * acc[nt][0] + acc[nt][1] * acc[nt][1];
        n1  += acc[nt][2] * acc[nt][2] + acc[nt][3] * acc[nt][3];
        xs0 += acc[nt][0] * e.x + acc[nt][1] * e.y;
        xs1 += acc[nt][2] * e.x + acc[nt][3] * e.y;
        ysp += e.x * e.x + e.y * e.y;
    }
    float n0q = quad_sum(n0), n1q = quad_sum(n1);
    float x0q = quad_sum(xs0), x1q = quad_sum(xs1);
    float yq = quad_sum(ysp);
    float* redN = (float*)(sm + SM_REDN);
    float* redX = (float*)(sm + SM_REDX);
    float* redY = (float*)(sm + SM_REDY);
    if (tig == 0) {
        redN[r0l * 2 + ch] = n0q; redN[r1l * 2 + ch] = n1q;
        redX[r0l * 2 + ch] = x0q; redX[r1l * 2 + ch] = x1q;
        if (g == 0 && rs == 0) redY[ch] = yq;
    }
    __syncthreads();
    float ne20 = redN[r0l * 2] + redN[r0l * 2 + 1];
    float ne21 = redN[r1l * 2] + redN[r1l * 2 + 1];
    float xss0 = redX[r0l * 2] + redX[r0l * 2 + 1];
    float xss1 = redX[r1l * 2] + redX[r1l * 2 + 1];
    float y2 = redY[0] + redY[1];

    float sc0, c10, c20, iv0, sc1, c11, c21, iv1;
    hadd_coef(ne20, xss0, y2, sc0, c10, c20, iv0);
    hadd_coef(ne21, xss1, y2, sc1, c11, c21, iv1);

    size_t r0g = (size_t)(row0 + r0l) * 128 + ch * 64;
    size_t r1g = (size_t)(row0 + r1l) * 128 + ch * 64;
#pragma unroll
    for (int nt = 0; nt < 8; nt++) {
        int col = nt * 8 + tig * 2;
        float2 e = *(const float2*)(eb + col);
        float2 o0, o1;
        o0.x = (c10 * sc0 * acc[nt][0] + c20 * e.x) * iv0;
        o0.y = (c10 * sc0 * acc[nt][1] + c20 * e.y) * iv0;
        o1.x = (c11 * sc1 * acc[nt][2] + c21 * e.x) * iv1;
        o1.y = (c11 * sc1 * acc[nt][3] + c21 * e.y) * iv1;
        *(float2*)(out + r0g + col) = o0;
        *(float2*)(out + r1g + col) = o1;
    }
}

// ---------------------------------------------------------------------------
extern "C" void kernel_launch(void* const* d_in, const int* in_sizes, int n_in,
                              void* d_out, int out_size) {
    const float* x     = (const float*)d_in[0];
    const float* adj   = (const float*)d_in[1];
    const float* embed = (const float*)d_in[2];
    const float* layer = (const float*)d_in[3];
    const float* ebias = (const float*)d_in[4];
    const float* lbias = (const float*)d_in[5];
    float* out = (float*)d_out;

    int N = in_sizes[0] / F;  // 8192

    __half* pVh;
    float* pC;
    cudaGetSymbolAddress((void**)&pVh, g_Vh);
    cudaGetSymbolAddress((void**)&pC, g_C);

    cudaFuncSetAttribute(k_mma1, cudaFuncAttributeMaxDynamicSharedMemorySize, smTot(128, 128));
    cudaFuncSetAttribute(k_mma3, cudaFuncAttributeMaxDynamicSharedMemorySize, smTot(256, 128));

    k_mma1<<<N / TM, NTH, smTot(128, 128)>>>(x, embed, ebias, pVh);
    k_spmm_fused<<<N / 8, 256>>>(adj, x, pVh, N);
    k_mma3<<<N / TM, NTH, smTot(256, 128)>>>(pC, layer, lbias, out);
}

// round 16
// speedup vs baseline: 1.0722x; 1.0722x over previous
#include <cuda_runtime.h>
#include <cuda_fp16.h>
#include <cuda_bf16.h>
#include <math.h>
#include <stdint.h>

#define EPSF 1e-7f
#define MAX_TANHF (1.0f - 1e-6f)

constexpr int F = 128;
constexpr int NMAX = 8192;
constexpr int TM = 32;    // rows per GEMM block
constexpr int NTH = 256;  // 8 warps

__device__ __half g_Vh[NMAX * F];     // log0(h), fp16 (spmm gather payload)
__device__ float  g_C [NMAX * 2 * F]; // log0([x ; neigh]) fp32

// ---------------------------------------------------------------------------
__device__ __forceinline__ float warp_sum(float v) {
    v += __shfl_xor_sync(0xffffffffu, v, 16);
    v += __shfl_xor_sync(0xffffffffu, v, 8);
    v += __shfl_xor_sync(0xffffffffu, v, 4);
    v += __shfl_xor_sync(0xffffffffu, v, 2);
    v += __shfl_xor_sync(0xffffffffu, v, 1);
    return v;
}
__device__ __forceinline__ float quad_sum(float v) {
    v += __shfl_xor_sync(0xffffffffu, v, 1);
    v += __shfl_xor_sync(0xffffffffu, v, 2);
    return v;
}
__device__ __forceinline__ float dot4(float4 a, float4 b) {
    return a.x * b.x + a.y * b.y + a.z * b.z + a.w * b.w;
}
__device__ __forceinline__ uint32_t bfpk(float a, float b) {
    __nv_bfloat162 t = __floats2bfloat162_rn(a, b);
    return *reinterpret_cast<uint32_t*>(&t);
}
__device__ __forceinline__ void split4(float4 v, uint2& hi, uint2& lo) {
    float h0 = __bfloat162float(__float2bfloat16_rn(v.x));
    float h1 = __bfloat162float(__float2bfloat16_rn(v.y));
    float h2 = __bfloat162float(__float2bfloat16_rn(v.z));
    float h3 = __bfloat162float(__float2bfloat16_rn(v.w));
    hi.x = bfpk(h0, h1); hi.y = bfpk(h2, h3);
    lo.x = bfpk(v.x - h0, v.y - h1); lo.y = bfpk(v.z - h2, v.w - h3);
}
__device__ __forceinline__ void mma_bf(float* c, const uint32_t* a,
                                       uint32_t b0, uint32_t b1) {
    asm volatile("mma.sync.aligned.m16n8k16.row.col.f32.bf16.bf16.f32 "
        "{%0,%1,%2,%3}, {%4,%5,%6,%7}, {%8,%9}, {%0,%1,%2,%3};"
        : "+f"(c[0]), "+f"(c[1]), "+f"(c[2]), "+f"(c[3])
        : "r"(a[0]), "r"(a[1]), "r"(a[2]), "r"(a[3]), "r"(b0), "r"(b1));
}
__device__ __forceinline__ void hadd_coef(float ne2, float xs, float y2,
                                          float& sc, float& c1, float& c2, float& inv) {
    float ne = fmaxf(sqrtf(ne2), EPSF);
    sc = tanhf(ne) / ne;
    float xy = sc * xs;
    float x2 = sc * sc * ne2;
    c1 = 1.f + 2.f * xy + y2;
    c2 = 1.f - x2;
    inv = 1.f / fmaxf(1.f + 2.f * xy + x2 * y2, EPSF);
}

// smem layout
__host__ __device__ constexpr int rsK(int K) { return K * 2 + 16; }
constexpr int SM_BIAS = 0;      // 128 floats
constexpr int SM_SROW = 512;    // 32 floats
constexpr int SM_REDN = 640;    // 32*4 floats [row][cq]
constexpr int SM_REDX = 1152;   // 32*4 floats
constexpr int SM_REDM = 1664;   // 32*4 floats
constexpr int SM_REDY = 2176;   // 4 floats
constexpr int SM_AHI  = 2304;
__host__ __device__ constexpr int smAlo(int KA) { return SM_AHI + TM * rsK(KA); }
__host__ __device__ constexpr int smBhi(int KA) { return smAlo(KA) + TM * rsK(KA); }
__host__ __device__ constexpr int smBlo(int KA) { return smBhi(KA) + 128 * rsK(128); }
__host__ __device__ constexpr int smTot(int KA) { return smBlo(KA) + 128 * rsK(128); }

// fill a 128-k B chunk: Bg[K][128] fp32 -> smem [n][k] bf16 hi/lo (stride rsK(128))
template <int KA>
__device__ __forceinline__ void fill_B128(char* sm, const float* __restrict__ Bg,
                                          int kbase, int tid) {
    constexpr int RB = rsK(128);
    for (int i = tid; i < 128 * 32; i += NTH) {
        int n = i & 127, k0 = (i >> 7) * 4;
        float4 v = make_float4(Bg[(size_t)(kbase + k0 + 0) * 128 + n],
                               Bg[(size_t)(kbase + k0 + 1) * 128 + n],
                               Bg[(size_t)(kbase + k0 + 2) * 128 + n],
                               Bg[(size_t)(kbase + k0 + 3) * 128 + n]);
        uint2 hi, lo;
        split4(v, hi, lo);
        *(uint2*)(sm + smBhi(KA) + n * RB + k0 * 2) = hi;
        *(uint2*)(sm + smBlo(KA) + n * RB + k0 * 2) = lo;
    }
}

// 8 kt (=128 k) of bf16-split MMAs; warp patch m16 x n32 (4 nt groups)
template <int RA, int RB>
__device__ __forceinline__ void mma_loop8(const char* Ah, const char* Al,
                                          const char* Bh, const char* Bl,
                                          float acc[4][4], int tig) {
#pragma unroll
    for (int kt = 0; kt < 8; kt++) {
        int kb = kt * 32 + tig * 4;
        uint32_t ahi[4], alo[4];
        ahi[0] = *(const uint32_t*)(Ah + kb);
        ahi[1] = *(const uint32_t*)(Ah + 8 * RA + kb);
        ahi[2] = *(const uint32_t*)(Ah + kb + 16);
        ahi[3] = *(const uint32_t*)(Ah + 8 * RA + kb + 16);
        alo[0] = *(const uint32_t*)(Al + kb);
        alo[1] = *(const uint32_t*)(Al + 8 * RA + kb);
        alo[2] = *(const uint32_t*)(Al + kb + 16);
        alo[3] = *(const uint32_t*)(Al + 8 * RA + kb + 16);
#pragma unroll
        for (int nt = 0; nt < 4; nt++) {
            const char* bh = Bh + nt * 8 * RB + kb;
            const char* bl = Bl + nt * 8 * RB + kb;
            uint32_t b0 = *(const uint32_t*)(bh);
            uint32_t b1 = *(const uint32_t*)(bh + 16);
            uint32_t l0 = *(const uint32_t*)(bl);
            uint32_t l1 = *(const uint32_t*)(bl + 16);
            mma_bf(acc[nt], ahi, b0, b1);
            mma_bf(acc[nt], ahi, l0, l1);
            mma_bf(acc[nt], alo, b0, b1);
        }
    }
}

// ---------------------------------------------------------------------------
// Stage 1: Vh = fp16( log0( h_add( exp0( log0(x) @ embed ), ebias ) ) )
// ---------------------------------------------------------------------------
__global__ void __launch_bounds__(NTH)
k_mma1(const float* __restrict__ x, const float* __restrict__ Bg,
       const float* __restrict__ ebias, __half* __restrict__ Vh) {
    constexpr int RA = rsK(128), RB = rsK(128);
    extern __shared__ char sm[];
    int tid = threadIdx.x, lane = tid & 31, w = tid >> 5;
    int g = lane >> 2, tig = lane & 3;
    int rs = w >> 2, cq = w & 3;      // row slab / col quarter
    int row0 = blockIdx.x * TM;

    if (tid < 128) ((float*)(sm + SM_BIAS))[tid] = ebias[tid];

    const float4* X4 = (const float4*)x;
    float* srow = (float*)(sm + SM_SROW);
    for (int rr = 0; rr < 4; rr++) {
        int row = w * 4 + rr;
        float4 xv = X4[(size_t)(row0 + row) * 32 + lane];
        float n2 = warp_sum(dot4(xv, xv));
        float n = fmaxf(sqrtf(n2), EPSF);
        if (lane == 0) srow[row] = atanhf(fminf(n, MAX_TANHF)) / n;
    }
    fill_B128<128>(sm, Bg, 0, tid);
    __syncthreads();

    for (int i = tid; i < TM * 32; i += NTH) {
        int row = i >> 5, cg = i & 31;
        float s = srow[row];
        float4 v = X4[(size_t)(row0 + row) * 32 + cg];
        v.x *= s; v.y *= s; v.z *= s; v.w *= s;
        uint2 hi, lo;
        split4(v, hi, lo);
        *(uint2*)(sm + SM_AHI     + row * RA + cg * 8) = hi;
        *(uint2*)(sm + smAlo(128) + row * RA + cg * 8) = lo;
    }
    __syncthreads();

    float acc[4][4] = {};
    mma_loop8<RA, RB>(sm + SM_AHI     + (rs * 16 + g) * RA,
                      sm + smAlo(128) + (rs * 16 + g) * RA,
                      sm + smBhi(128) + (cq * 32 + g) * RB,
                      sm + smBlo(128) + (cq * 32 + g) * RB, acc, tig);

    // ---- epilogue (cross-warp reductions via smem [row][cq]) ----
    int r0l = rs * 16 + g, r1l = r0l + 8;
    const float* eb = (const float*)(sm + SM_BIAS) + cq * 32;
    float n0 = 0, n1 = 0, xs0 = 0, xs1 = 0, ysp = 0;
#pragma unroll
    for (int nt = 0; nt < 4; nt++) {
        float2 e = *(const float2*)(eb + nt * 8 + tig * 2);
        n0  += acc[nt][0] * acc[nt][0] + acc[nt][1] * acc[nt][1];
        n1  += acc[nt][2] * acc[nt][2] + acc[nt][3] * acc[nt][3];
        xs0 += acc[nt][0] * e.x + acc[nt][1] * e.y;
        xs1 += acc[nt][2] * e.x + acc[nt][3] * e.y;
        ysp += e.x * e.x + e.y * e.y;
    }
    float n0q = quad_sum(n0), n1q = quad_sum(n1);
    float x0q = quad_sum(xs0), x1q = quad_sum(xs1);
    float yq = quad_sum(ysp);
    float* redN = (float*)(sm + SM_REDN);
    float* redX = (float*)(sm + SM_REDX);
    float* redY = (float*)(sm + SM_REDY);
    if (tig == 0) {
        redN[r0l * 4 + cq] = n0q; redN[r1l * 4 + cq] = n1q;
        redX[r0l * 4 + cq] = x0q; redX[r1l * 4 + cq] = x1q;
        if (g == 0 && rs == 0) redY[cq] = yq;
    }
    __syncthreads();
    float ne20 = redN[r0l * 4] + redN[r0l * 4 + 1] + redN[r0l * 4 + 2] + redN[r0l * 4 + 3];
    float ne21 = redN[r1l * 4] + redN[r1l * 4 + 1] + redN[r1l * 4 + 2] + redN[r1l * 4 + 3];
    float xss0 = redX[r0l * 4] + redX[r0l * 4 + 1] + redX[r0l * 4 + 2] + redX[r0l * 4 + 3];
    float xss1 = redX[r1l * 4] + redX[r1l * 4 + 1] + redX[r1l * 4 + 2] + redX[r1l * 4 + 3];
    float y2 = redY[0] + redY[1] + redY[2] + redY[3];

    float sc0, c10, c20, iv0, sc1, c11, c21, iv1;
    hadd_coef(ne20, xss0, y2, sc0, c10, c20, iv0);
    hadd_coef(ne21, xss1, y2, sc1, c11, c21, iv1);

    float m0 = 0, m1 = 0;
#pragma unroll
    for (int nt = 0; nt < 4; nt++) {
        float2 e = *(const float2*)(eb + nt * 8 + tig * 2);
        float r00 = (c10 * sc0 * acc[nt][0] + c20 * e.x) * iv0;
        float r01 = (c10 * sc0 * acc[nt][1] + c20 * e.y) * iv0;
        float r10 = (c11 * sc1 * acc[nt][2] + c21 * e.x) * iv1;
        float r11 = (c11 * sc1 * acc[nt][3] + c21 * e.y) * iv1;
        m0 += r00 * r00 + r01 * r01;
        m1 += r10 * r10 + r11 * r11;
        acc[nt][0] = r00; acc[nt][1] = r01; acc[nt][2] = r10; acc[nt][3] = r11;
    }
    float m0q = quad_sum(m0), m1q = quad_sum(m1);
    float* redM = (float*)(sm + SM_REDM);
    if (tig == 0) { redM[r0l * 4 + cq] = m0q; redM[r1l * 4 + cq] = m1q; }
    __syncthreads();
    float nr0 = fmaxf(sqrtf(redM[r0l * 4] + redM[r0l * 4 + 1] + redM[r0l * 4 + 2] + redM[r0l * 4 + 3]), EPSF);
    float nr1 = fmaxf(sqrtf(redM[r1l * 4] + redM[r1l * 4 + 1] + redM[r1l * 4 + 2] + redM[r1l * 4 + 3]), EPSF);
    float s0 = atanhf(fminf(nr0, MAX_TANHF)) / nr0;
    float s1 = atanhf(fminf(nr1, MAX_TANHF)) / nr1;

    size_t r0g = (size_t)(row0 + r0l) * 128 + cq * 32;
    size_t r1g = (size_t)(row0 + r1l) * 128 + cq * 32;
#pragma unroll
    for (int nt = 0; nt < 4; nt++) {
        int col = nt * 8 + tig * 2;
        half2 h0 = __floats2half2_rn(acc[nt][0] * s0, acc[nt][1] * s0);
        half2 h1 = __floats2half2_rn(acc[nt][2] * s1, acc[nt][3] * s1);
        *(uint32_t*)(Vh + r0g + col) = *reinterpret_cast<uint32_t*>(&h0);
        *(uint32_t*)(Vh + r1g + col) = *reinterpret_cast<uint32_t*>(&h1);
    }
}

// ---------------------------------------------------------------------------
// Stage 2: C = log0([x ; exp0(adj @ Vh)]) — warp/row, fp16 gathers
// ---------------------------------------------------------------------------
__global__ void k_spmm_fused(const float* __restrict__ adj,
                             const float* __restrict__ x,
                             const __half* __restrict__ Vh, int N) {
    int warp = (blockIdx.x * blockDim.x + threadIdx.x) >> 5;
    int lane = threadIdx.x & 31;
    if (warp >= N) return;

    const uint2* V2 = (const uint2*)Vh;
    const float4* arow = (const float4*)(adj + (size_t)warp * N);
    float4 acc = make_float4(0.f, 0.f, 0.f, 0.f);

    int nq = N / 4;
    float4 a_cur = __ldcs(arow + lane);
    for (int jb = 0; jb < nq; jb += 32) {
        float4 a_nxt = make_float4(0.f, 0.f, 0.f, 0.f);
        if (jb + 32 < nq) a_nxt = __ldcs(arow + jb + 32 + lane);
#pragma unroll
        for (int c = 0; c < 4; c++) {
            float av = (c == 0) ? a_cur.x : (c == 1) ? a_cur.y
                                : (c == 2) ? a_cur.z : a_cur.w;
            unsigned m = __ballot_sync(0xffffffffu, av != 0.0f);
            while (m) {
                int b = __ffs(m) - 1;
                m &= m - 1;
                float aval = __shfl_sync(0xffffffffu, av, b);
                int j = (jb + b) * 4 + c;
                uint2 vr = V2[(size_t)j * 32 + lane];
                half2 h0 = *reinterpret_cast<half2*>(&vr.x);
                half2 h1 = *reinterpret_cast<half2*>(&vr.y);
                float2 f0 = __half22float2(h0);
                float2 f1 = __half22float2(h1);
                acc.x += aval * f0.x;
                acc.y += aval * f0.y;
                acc.z += aval * f1.x;
                acc.w += aval * f1.y;
            }
        }
        a_cur = a_nxt;
    }

    float nn2 = warp_sum(dot4(acc, acc));
    float nn = fmaxf(sqrtf(nn2), EPSF);
    float e = tanhf(nn) / nn;
    float4 ng = make_float4(acc.x * e, acc.y * e, acc.z * e, acc.w * e);

    float4 xv = ((const float4*)x)[(size_t)warp * 32 + lane];
    float nx2 = warp_sum(dot4(xv, xv));
    float ng2 = e * e * nn2;
    float nc = fmaxf(sqrtf(nx2 + ng2), EPSF);
    float s = atanhf(fminf(nc, MAX_TANHF)) / nc;

    float4* C4 = (float4*)g_C;
    C4[(size_t)warp * 64 + lane]      = make_float4(xv.x * s, xv.y * s, xv.z * s, xv.w * s);
    C4[(size_t)warp * 64 + 32 + lane] = make_float4(ng.x * s, ng.y * s, ng.z * s, ng.w * s);
}

// ---------------------------------------------------------------------------
// Stage 3: out = h_add( exp0( C @ layer ), lbias ), K=256, B chunked 2 x 128k
// ---------------------------------------------------------------------------
__global__ void __launch_bounds__(NTH)
k_mma3(const float* __restrict__ A, const float* __restrict__ Bg,
       const float* __restrict__ lbias, float* __restrict__ out) {
    constexpr int RA = rsK(256), RB = rsK(128);
    extern __shared__ char sm[];
    int tid = threadIdx.x, lane = tid & 31, w = tid >> 5;
    int g = lane >> 2, tig = lane & 3;
    int rs = w >> 2, cq = w & 3;
    int row0 = blockIdx.x * TM;

    if (tid < 128) ((float*)(sm + SM_BIAS))[tid] = lbias[tid];

    // A fill: rows of g_C, full K=256
    const float4* A4 = (const float4*)A;
    for (int i = tid; i < TM * 64; i += NTH) {
        int row = i >> 6, cg = i & 63;
        float4 v = A4[(size_t)(row0 + row) * 64 + cg];
        uint2 hi, lo;
        split4(v, hi, lo);
        *(uint2*)(sm + SM_AHI     + row * RA + cg * 8) = hi;
        *(uint2*)(sm + smAlo(256) + row * RA + cg * 8) = lo;
    }

    float acc[4][4] = {};
    const char* Ah = sm + SM_AHI     + (rs * 16 + g) * RA;
    const char* Al = sm + smAlo(256) + (rs * 16 + g) * RA;
    const char* Bh = sm + smBhi(256) + (cq * 32 + g) * RB;
    const char* Bl = sm + smBlo(256) + (cq * 32 + g) * RB;
#pragma unroll
    for (int kc = 0; kc < 2; kc++) {
        __syncthreads();
        fill_B128<256>(sm, Bg, kc * 128, tid);
        __syncthreads();
        mma_loop8<RA, RB>(Ah + kc * 256, Al + kc * 256, Bh, Bl, acc, tig);
    }

    int r0l = rs * 16 + g, r1l = r0l + 8;
    const float* eb = (const float*)(sm + SM_BIAS) + cq * 32;
    float n0 = 0, n1 = 0, xs0 = 0, xs1 = 0, ysp = 0;
#pragma unroll
    for (int nt = 0; nt < 4; nt++) {
        float2 e = *(const float2*)(eb + nt * 8 + tig * 2);
        n0  += acc[nt][0] * acc[nt][0] + acc[nt][1] * acc[nt][1];
        n1  += acc[nt][2] * acc[nt][2] + acc[nt][3] * acc[nt][3];
        xs0 += acc[nt][0] * e.x + acc[nt][1] * e.y;
        xs1 += acc[nt][2] * e.x + acc[nt][3] * e.y;
        ysp += e.x * e.x + e.y * e.y;
    }
    float n0q = quad_sum(n0), n1q = quad_sum(n1);
    float x0q = quad_sum(xs0), x1q = quad_sum(xs1);
    float yq = quad_sum(ysp);
    float* redN = (float*)(sm + SM_REDN);
    float* redX = (float*)(sm + SM_REDX);
    float* redY = (float*)(sm + SM_REDY);
    if (tig == 0) {
        redN[r0l * 4 + cq] = n0q; redN[r1l * 4 + cq] = n1q;
        redX[r0l * 4 + cq] = x0q; redX[r1l * 4 + cq] = x1q;
        if (g == 0 && rs == 0) redY[cq] = yq;
    }
    __syncthreads();
    float ne20 = redN[r0l * 4] + redN[r0l * 4 + 1] + redN[r0l * 4 + 2] + redN[r0l * 4 + 3];
    float ne21 = redN[r1l * 4] + redN[r1l * 4 + 1] + redN[r1l * 4 + 2] + redN[r1l * 4 + 3];
    float xss0 = redX[r0l * 4] + redX[r0l * 4 + 1] + redX[r0l * 4 + 2] + redX[r0l * 4 + 3];
    float xss1 = redX[r1l * 4] + redX[r1l * 4 + 1] + redX[r1l * 4 + 2] + redX[r1l * 4 + 3];
    float y2 = redY[0] + redY[1] + redY[2] + redY[3];

    float sc0, c10, c20, iv0, sc1, c11, c21, iv1;
    hadd_coef(ne20, xss0, y2, sc0, c10, c20, iv0);
    hadd_coef(ne21, xss1, y2, sc1, c11, c21, iv1);

    size_t r0g = (size_t)(row0 + r0l) * 128 + cq * 32;
    size_t r1g = (size_t)(row0 + r1l) * 128 + cq * 32;
#pragma unroll
    for (int nt = 0; nt < 4; nt++) {
        int col = nt * 8 + tig * 2;
        float2 e = *(const float2*)(eb + col);
        float2 o0, o1;
        o0.x = (c10 * sc0 * acc[nt][0] + c20 * e.x) * iv0;
        o0.y = (c10 * sc0 * acc[nt][1] + c20 * e.y) * iv0;
        o1.x = (c11 * sc1 * acc[nt][2] + c21 * e.x) * iv1;
        o1.y = (c11 * sc1 * acc[nt][3] + c21 * e.y) * iv1;
        *(float2*)(out + r0g + col) = o0;
        *(float2*)(out + r1g + col) = o1;
    }
}

// ---------------------------------------------------------------------------
extern "C" void kernel_launch(void* const* d_in, const int* in_sizes, int n_in,
                              void* d_out, int out_size) {
    const float* x     = (const float*)d_in[0];
    const float* adj   = (const float*)d_in[1];
    const float* embed = (const float*)d_in[2];
    const float* layer = (const float*)d_in[3];
    const float* ebias = (const float*)d_in[4];
    const float* lbias = (const float*)d_in[5];
    float* out = (float*)d_out;

    int N = in_sizes[0] / F;  // 8192

    __half* pVh;
    float* pC;
    cudaGetSymbolAddress((void**)&pVh, g_Vh);
    cudaGetSymbolAddress((void**)&pC, g_C);

    cudaFuncSetAttribute(k_mma1, cudaFuncAttributeMaxDynamicSharedMemorySize, smTot(128));
    cudaFuncSetAttribute(k_mma3, cudaFuncAttributeMaxDynamicSharedMemorySize, smTot(256));

    k_mma1<<<N / TM, NTH, smTot(128)>>>(x, embed, ebias, pVh);
    k_spmm_fused<<<N / 8, 256>>>(adj, x, pVh, N);
    k_mma3<<<N / TM, NTH, smTot(256)>>>(pC, layer, lbias, out);
}